// round 2
// baseline (speedup 1.0000x reference)
#include <cuda_runtime.h>
#include <math.h>

#define HIDDEN 128
#define NGRAPH 4096
#define POOL_DIM (3 * HIDDEN)

// Scratch for pooled features [NGRAPH, 3*HIDDEN] = 6 MB
__device__ float g_pooled[NGRAPH * POOL_DIM];

// ---------------------------------------------------------------------------
// Phase A: one block per graph (batch sorted -> contiguous range via binary
// search). 512 threads = 16 row-groups x 32 lanes; each lane owns 4 channels
// via float4. Streaming loads (__ldcs): x has zero reuse, keep it out of L2.
// ---------------------------------------------------------------------------
__device__ __forceinline__ int batch_val(const int* __restrict__ w, int i, bool is64) {
    return is64 ? w[2 * i] : w[i];
}

__global__ void __launch_bounds__(512)
pool_kernel(const float* __restrict__ x, const int* __restrict__ batch_raw, int n_nodes) {
    const int g = blockIdx.x;
    __shared__ int s_range[2];

    // int64 vs int32 detection (little-endian, ids < 2^31)
    const bool is64 = (batch_raw[n_nodes - 1] == 0) && (batch_raw[n_nodes - 2] != 0);

    if (threadIdx.x == 0) {
        int lo = 0, hi = n_nodes;
        while (lo < hi) { int mid = (lo + hi) >> 1;
            if (batch_val(batch_raw, mid, is64) < g) lo = mid + 1; else hi = mid; }
        s_range[0] = lo;
    }
    if (threadIdx.x == 32) {
        int lo = 0, hi = n_nodes;
        while (lo < hi) { int mid = (lo + hi) >> 1;
            if (batch_val(batch_raw, mid, is64) < g + 1) lo = mid + 1; else hi = mid; }
        s_range[1] = lo;
    }
    __syncthreads();
    const int start = s_range[0];
    const int end   = s_range[1];

    const int lane = threadIdx.x & 31;
    const int h    = threadIdx.x >> 5;   // row group 0..15

    const float4* xv = (const float4*)x;   // 32 float4 per row

    const float NEG = -3.402823466e38f;
    float4 s0 = make_float4(0.f, 0.f, 0.f, 0.f);
    float4 s1 = make_float4(0.f, 0.f, 0.f, 0.f);
    float4 m0 = make_float4(NEG, NEG, NEG, NEG);
    float4 m1 = make_float4(NEG, NEG, NEG, NEG);

    int i = start + h;
    for (; i + 16 < end; i += 32) {
        float4 v0 = __ldcs(xv + (size_t)i * 32 + lane);
        float4 v1 = __ldcs(xv + (size_t)(i + 16) * 32 + lane);
        s0.x += v0.x; s0.y += v0.y; s0.z += v0.z; s0.w += v0.w;
        m0.x = fmaxf(m0.x, v0.x); m0.y = fmaxf(m0.y, v0.y);
        m0.z = fmaxf(m0.z, v0.z); m0.w = fmaxf(m0.w, v0.w);
        s1.x += v1.x; s1.y += v1.y; s1.z += v1.z; s1.w += v1.w;
        m1.x = fmaxf(m1.x, v1.x); m1.y = fmaxf(m1.y, v1.y);
        m1.z = fmaxf(m1.z, v1.z); m1.w = fmaxf(m1.w, v1.w);
    }
    for (; i < end; i += 16) {
        float4 v0 = __ldcs(xv + (size_t)i * 32 + lane);
        s0.x += v0.x; s0.y += v0.y; s0.z += v0.z; s0.w += v0.w;
        m0.x = fmaxf(m0.x, v0.x); m0.y = fmaxf(m0.y, v0.y);
        m0.z = fmaxf(m0.z, v0.z); m0.w = fmaxf(m0.w, v0.w);
    }
    float4 S = make_float4(s0.x + s1.x, s0.y + s1.y, s0.z + s1.z, s0.w + s1.w);
    float4 M = make_float4(fmaxf(m0.x, m1.x), fmaxf(m0.y, m1.y),
                           fmaxf(m0.z, m1.z), fmaxf(m0.w, m1.w));

    __shared__ float4 s_sum[16][32];
    __shared__ float4 s_max[16][32];
    s_sum[h][lane] = S;
    s_max[h][lane] = M;
    __syncthreads();

    // stage 1: 128 threads reduce 16 -> 4 partials
    if (threadIdx.x < 128) {
        const int part = threadIdx.x >> 5;
        const int l    = threadIdx.x & 31;
        float4 a = s_sum[part][l], b = s_sum[part + 4][l],
               c = s_sum[part + 8][l], d = s_sum[part + 12][l];
        float4 r = make_float4(a.x + b.x + c.x + d.x, a.y + b.y + c.y + d.y,
                               a.z + b.z + c.z + d.z, a.w + b.w + c.w + d.w);
        s_sum[part][l] = r;
        float4 am = s_max[part][l], bm = s_max[part + 4][l],
               cm = s_max[part + 8][l], dm = s_max[part + 12][l];
        float4 rm = make_float4(fmaxf(fmaxf(am.x, bm.x), fmaxf(cm.x, dm.x)),
                                fmaxf(fmaxf(am.y, bm.y), fmaxf(cm.y, dm.y)),
                                fmaxf(fmaxf(am.z, bm.z), fmaxf(cm.z, dm.z)),
                                fmaxf(fmaxf(am.w, bm.w), fmaxf(cm.w, dm.w)));
        s_max[part][l] = rm;
    }
    __syncthreads();

    // stage 2: 32 threads finalize + write pooled features
    if (threadIdx.x < 32) {
        const int l = threadIdx.x;
        float4 a = s_sum[0][l], b = s_sum[1][l], c = s_sum[2][l], d = s_sum[3][l];
        float4 SS = make_float4(a.x + b.x + c.x + d.x, a.y + b.y + c.y + d.y,
                                a.z + b.z + c.z + d.z, a.w + b.w + c.w + d.w);
        float4 am = s_max[0][l], bm = s_max[1][l], cm = s_max[2][l], dm = s_max[3][l];
        float4 MM = make_float4(fmaxf(fmaxf(am.x, bm.x), fmaxf(cm.x, dm.x)),
                                fmaxf(fmaxf(am.y, bm.y), fmaxf(cm.y, dm.y)),
                                fmaxf(fmaxf(am.z, bm.z), fmaxf(cm.z, dm.z)),
                                fmaxf(fmaxf(am.w, bm.w), fmaxf(cm.w, dm.w)));
        const int cnt = end - start;
        const float inv = 1.0f / fmaxf((float)cnt, 1.0f);
        float4 mean = make_float4(SS.x * inv, SS.y * inv, SS.z * inv, SS.w * inv);
        if (cnt <= 0) MM = make_float4(0.f, 0.f, 0.f, 0.f);
        float4* o = (float4*)(g_pooled + (size_t)g * POOL_DIM);
        o[l]      = mean;
        o[32 + l] = MM;
        o[64 + l] = SS;
    }
}

// ---------------------------------------------------------------------------
// Phase B: fused GEMM [4096,384]x[384,128] + bias + LayerNorm + exact GELU.
// 128 blocks x 512 threads (16 warps/SM). Each thread: column j, 8 rows via
// 4 packed f32x2 accumulators (Blackwell dual-fp32 FMA, PTX-only).
// p-tile reads are warp-uniform broadcasts; w reads are coalesced.
// ---------------------------------------------------------------------------
__global__ void __launch_bounds__(512)
gemm_ln_gelu_kernel(const float* __restrict__ W, const float* __restrict__ bias,
                    const float* __restrict__ gamma, const float* __restrict__ beta,
                    float* __restrict__ out) {
    const int GT = 32;   // graph rows per block
    const int KT = 64;   // k tile

    __shared__ float sW[KT][HIDDEN];      // 32 KB
    __shared__ float sP[KT][GT + 4];      // transposed pooled tile (stride 36 = 16B aligned)
    __shared__ float sH[GT][HIDDEN + 4];  // post-GEMM h for LN

    const int g0 = blockIdx.x * GT;
    const int j  = threadIdx.x & (HIDDEN - 1);  // output column
    const int rg = threadIdx.x >> 7;            // 0..3: rows [rg*8, rg*8+8)

    unsigned long long acc2[4];
#pragma unroll
    for (int r = 0; r < 4; r++) acc2[r] = 0ull;

    for (int kt = 0; kt < POOL_DIM; kt += KT) {
        __syncthreads();
        for (int idx = threadIdx.x; idx < KT * HIDDEN; idx += 512) {
            int kk = idx >> 7, col = idx & (HIDDEN - 1);
            sW[kk][col] = W[(size_t)(kt + kk) * HIDDEN + col];
        }
        for (int idx = threadIdx.x; idx < GT * KT; idx += 512) {
            int r = idx / KT, kk = idx - r * KT;
            sP[kk][r] = g_pooled[(size_t)(g0 + r) * POOL_DIM + kt + kk];
        }
        __syncthreads();

#pragma unroll 4
        for (int kk = 0; kk < KT; kk++) {
            float w = sW[kk][j];
            unsigned long long w2;
            asm("mov.b64 %0, {%1, %1};" : "=l"(w2) : "f"(w));
            const ulonglong2* p2 = (const ulonglong2*)&sP[kk][rg * 8];
            ulonglong2 pa = p2[0], pb = p2[1];
            asm("fma.rn.f32x2 %0, %1, %2, %0;" : "+l"(acc2[0]) : "l"(pa.x), "l"(w2));
            asm("fma.rn.f32x2 %0, %1, %2, %0;" : "+l"(acc2[1]) : "l"(pa.y), "l"(w2));
            asm("fma.rn.f32x2 %0, %1, %2, %0;" : "+l"(acc2[2]) : "l"(pb.x), "l"(w2));
            asm("fma.rn.f32x2 %0, %1, %2, %0;" : "+l"(acc2[3]) : "l"(pb.y), "l"(w2));
        }
    }

    float bj = bias[j];
#pragma unroll
    for (int r = 0; r < 4; r++) {
        float lo, hi;
        asm("mov.b64 {%0, %1}, %2;" : "=f"(lo), "=f"(hi) : "l"(acc2[r]));
        sH[rg * 8 + 2 * r][j]     = lo + bj;
        sH[rg * 8 + 2 * r + 1][j] = hi + bj;
    }
    __syncthreads();

    // LayerNorm + exact GELU: 16 warps, 2 rows each; lane covers 4 columns
    const int warp = threadIdx.x >> 5, lane = threadIdx.x & 31;
    for (int row = warp; row < GT; row += 16) {
        float v[4];
#pragma unroll
        for (int q = 0; q < 4; q++) v[q] = sH[row][lane + 32 * q];

        float s = v[0] + v[1] + v[2] + v[3];
#pragma unroll
        for (int o = 16; o > 0; o >>= 1) s += __shfl_xor_sync(0xffffffffu, s, o);
        float mu = s * (1.0f / 128.0f);

        float vs = 0.f;
#pragma unroll
        for (int q = 0; q < 4; q++) { float d = v[q] - mu; vs += d * d; }
#pragma unroll
        for (int o = 16; o > 0; o >>= 1) vs += __shfl_xor_sync(0xffffffffu, vs, o);
        float inv = rsqrtf(vs * (1.0f / 128.0f) + 1e-5f);

#pragma unroll
        for (int q = 0; q < 4; q++) {
            int col = lane + 32 * q;
            float y = (v[q] - mu) * inv * gamma[col] + beta[col];
            float ge = 0.5f * y * (1.0f + erff(y * 0.70710678118654752f));
            out[(size_t)(g0 + row) * HIDDEN + col] = ge;
        }
    }
}

// ---------------------------------------------------------------------------
extern "C" void kernel_launch(void* const* d_in, const int* in_sizes, int n_in,
                              void* d_out, int out_size) {
    int ix = -1;
    long long maxsz = -1;
    for (int i = 0; i < n_in; i++)
        if ((long long)in_sizes[i] > maxsz) { maxsz = in_sizes[i]; ix = i; }
    const int n_nodes = (int)(maxsz / HIDDEN);

    int ib = -1, iw = -1, vecs[3] = {-1, -1, -1}; int nv = 0;
    for (int i = 0; i < n_in; i++) {
        if (i == ix) continue;
        if (in_sizes[i] == n_nodes) ib = i;
        else if (in_sizes[i] == POOL_DIM * HIDDEN) iw = i;
        else if (in_sizes[i] == HIDDEN && nv < 3) vecs[nv++] = i;
    }

    const float* x     = (const float*)d_in[ix];
    const int*   batch = (const int*)d_in[ib];
    const float* W     = (const float*)d_in[iw];
    const float* b     = (const float*)d_in[vecs[0]];
    const float* gamma = (const float*)d_in[vecs[1]];
    const float* beta  = (const float*)d_in[vecs[2]];
    float* out = (float*)d_out;

    pool_kernel<<<NGRAPH, 512>>>(x, batch, n_nodes);
    gemm_ln_gelu_kernel<<<NGRAPH / 32, 512>>>(W, b, gamma, beta, out);
}

// round 3
// speedup vs baseline: 1.0176x; 1.0176x over previous
#include <cuda_runtime.h>
#include <math.h>

#define HIDDEN 128
#define NGRAPH 4096
#define POOL_DIM (3 * HIDDEN)

// Scratch for pooled features [NGRAPH, 3*HIDDEN] = 6 MB
__device__ float g_pooled[NGRAPH * POOL_DIM];

// ---------------------------------------------------------------------------
// Phase A: one block per graph (batch sorted -> contiguous range via binary
// search). 512 threads = 16 row-groups x 32 lanes; lane owns 4 channels via
// float4. 4x unroll -> 4 independent 512B loads in flight per warp (MLP 4).
// ---------------------------------------------------------------------------
__device__ __forceinline__ int batch_val(const int* __restrict__ w, int i, bool is64) {
    return is64 ? w[2 * i] : w[i];
}

__global__ void __launch_bounds__(512)
pool_kernel(const float* __restrict__ x, const int* __restrict__ batch_raw, int n_nodes) {
    const int g = blockIdx.x;
    __shared__ int s_range[2];

    // int64 vs int32 detection (little-endian, ids < 2^31)
    const bool is64 = (batch_raw[n_nodes - 1] == 0) && (batch_raw[n_nodes - 2] != 0);

    if (threadIdx.x == 0) {
        int lo = 0, hi = n_nodes;
        while (lo < hi) { int mid = (lo + hi) >> 1;
            if (batch_val(batch_raw, mid, is64) < g) lo = mid + 1; else hi = mid; }
        s_range[0] = lo;
    }
    if (threadIdx.x == 32) {
        int lo = 0, hi = n_nodes;
        while (lo < hi) { int mid = (lo + hi) >> 1;
            if (batch_val(batch_raw, mid, is64) < g + 1) lo = mid + 1; else hi = mid; }
        s_range[1] = lo;
    }
    __syncthreads();
    const int start = s_range[0];
    const int end   = s_range[1];

    const int lane = threadIdx.x & 31;
    const int h    = threadIdx.x >> 5;   // row group 0..15

    const float4* xv = (const float4*)x;   // 32 float4 per row

    const float NEG = -3.402823466e38f;
    float4 s0 = make_float4(0.f, 0.f, 0.f, 0.f), s1 = s0, s2 = s0, s3 = s0;
    float4 m0 = make_float4(NEG, NEG, NEG, NEG), m1 = m0, m2 = m0, m3 = m0;

    int i = start + h;
    for (; i + 48 < end; i += 64) {
        float4 v0 = __ldcs(xv + (size_t)i * 32 + lane);
        float4 v1 = __ldcs(xv + (size_t)(i + 16) * 32 + lane);
        float4 v2 = __ldcs(xv + (size_t)(i + 32) * 32 + lane);
        float4 v3 = __ldcs(xv + (size_t)(i + 48) * 32 + lane);
        s0.x += v0.x; s0.y += v0.y; s0.z += v0.z; s0.w += v0.w;
        m0.x = fmaxf(m0.x, v0.x); m0.y = fmaxf(m0.y, v0.y);
        m0.z = fmaxf(m0.z, v0.z); m0.w = fmaxf(m0.w, v0.w);
        s1.x += v1.x; s1.y += v1.y; s1.z += v1.z; s1.w += v1.w;
        m1.x = fmaxf(m1.x, v1.x); m1.y = fmaxf(m1.y, v1.y);
        m1.z = fmaxf(m1.z, v1.z); m1.w = fmaxf(m1.w, v1.w);
        s2.x += v2.x; s2.y += v2.y; s2.z += v2.z; s2.w += v2.w;
        m2.x = fmaxf(m2.x, v2.x); m2.y = fmaxf(m2.y, v2.y);
        m2.z = fmaxf(m2.z, v2.z); m2.w = fmaxf(m2.w, v2.w);
        s3.x += v3.x; s3.y += v3.y; s3.z += v3.z; s3.w += v3.w;
        m3.x = fmaxf(m3.x, v3.x); m3.y = fmaxf(m3.y, v3.y);
        m3.z = fmaxf(m3.z, v3.z); m3.w = fmaxf(m3.w, v3.w);
    }
    for (; i < end; i += 16) {
        float4 v0 = __ldcs(xv + (size_t)i * 32 + lane);
        s0.x += v0.x; s0.y += v0.y; s0.z += v0.z; s0.w += v0.w;
        m0.x = fmaxf(m0.x, v0.x); m0.y = fmaxf(m0.y, v0.y);
        m0.z = fmaxf(m0.z, v0.z); m0.w = fmaxf(m0.w, v0.w);
    }
    float4 S = make_float4(s0.x + s1.x + s2.x + s3.x, s0.y + s1.y + s2.y + s3.y,
                           s0.z + s1.z + s2.z + s3.z, s0.w + s1.w + s2.w + s3.w);
    float4 M = make_float4(fmaxf(fmaxf(m0.x, m1.x), fmaxf(m2.x, m3.x)),
                           fmaxf(fmaxf(m0.y, m1.y), fmaxf(m2.y, m3.y)),
                           fmaxf(fmaxf(m0.z, m1.z), fmaxf(m2.z, m3.z)),
                           fmaxf(fmaxf(m0.w, m1.w), fmaxf(m2.w, m3.w)));

    __shared__ float4 s_sum[16][32];
    __shared__ float4 s_max[16][32];
    s_sum[h][lane] = S;
    s_max[h][lane] = M;
    __syncthreads();

    if (threadIdx.x < 128) {
        const int part = threadIdx.x >> 5;
        const int l    = threadIdx.x & 31;
        float4 a = s_sum[part][l], b = s_sum[part + 4][l],
               c = s_sum[part + 8][l], d = s_sum[part + 12][l];
        s_sum[part][l] = make_float4(a.x + b.x + c.x + d.x, a.y + b.y + c.y + d.y,
                                     a.z + b.z + c.z + d.z, a.w + b.w + c.w + d.w);
        float4 am = s_max[part][l], bm = s_max[part + 4][l],
               cm = s_max[part + 8][l], dm = s_max[part + 12][l];
        s_max[part][l] = make_float4(fmaxf(fmaxf(am.x, bm.x), fmaxf(cm.x, dm.x)),
                                     fmaxf(fmaxf(am.y, bm.y), fmaxf(cm.y, dm.y)),
                                     fmaxf(fmaxf(am.z, bm.z), fmaxf(cm.z, dm.z)),
                                     fmaxf(fmaxf(am.w, bm.w), fmaxf(cm.w, dm.w)));
    }
    __syncthreads();

    if (threadIdx.x < 32) {
        const int l = threadIdx.x;
        float4 a = s_sum[0][l], b = s_sum[1][l], c = s_sum[2][l], d = s_sum[3][l];
        float4 SS = make_float4(a.x + b.x + c.x + d.x, a.y + b.y + c.y + d.y,
                                a.z + b.z + c.z + d.z, a.w + b.w + c.w + d.w);
        float4 am = s_max[0][l], bm = s_max[1][l], cm = s_max[2][l], dm = s_max[3][l];
        float4 MM = make_float4(fmaxf(fmaxf(am.x, bm.x), fmaxf(cm.x, dm.x)),
                                fmaxf(fmaxf(am.y, bm.y), fmaxf(cm.y, dm.y)),
                                fmaxf(fmaxf(am.z, bm.z), fmaxf(cm.z, dm.z)),
                                fmaxf(fmaxf(am.w, bm.w), fmaxf(cm.w, dm.w)));
        const int cnt = end - start;
        const float inv = 1.0f / fmaxf((float)cnt, 1.0f);
        float4 mean = make_float4(SS.x * inv, SS.y * inv, SS.z * inv, SS.w * inv);
        if (cnt <= 0) MM = make_float4(0.f, 0.f, 0.f, 0.f);
        float4* o = (float4*)(g_pooled + (size_t)g * POOL_DIM);
        o[l]      = mean;
        o[32 + l] = MM;
        o[64 + l] = SS;
    }
}

// ---------------------------------------------------------------------------
// Phase B: fused GEMM [4096,384]x[384,128] + bias + LayerNorm + exact GELU.
// W is NOT staged in smem: read via __ldg (192KB fits L1 per SM; coalesced).
// Pooled tile (transposed) in smem; each thread's 8 rows = two warp-uniform
// LDS.128 broadcasts. Inner loop per k: 1 LDG + 2 LDS + 4 packed f32x2 FMA,
// unroll 8 -> 8 LDGs in flight. Only 2 __syncthreads in the whole main loop.
// ---------------------------------------------------------------------------
__global__ void __launch_bounds__(512)
gemm_ln_gelu_kernel(const float* __restrict__ W, const float* __restrict__ bias,
                    const float* __restrict__ gamma, const float* __restrict__ beta,
                    float* __restrict__ out) {
    const int GT = 32;    // graph rows per block
    const int KT = 128;   // k tile

    __shared__ float sP[KT][GT + 4];      // [kk][row], stride 36 floats (144B, 16B-mult)
    __shared__ float sH[GT][HIDDEN + 4];  // post-GEMM h for LN

    const int g0 = blockIdx.x * GT;
    const int j  = threadIdx.x & (HIDDEN - 1);  // output column
    const int rg = threadIdx.x >> 7;            // 0..3: rows [rg*8, rg*8+8)

    unsigned long long acc2[4];
#pragma unroll
    for (int r = 0; r < 4; r++) acc2[r] = 0ull;

    for (int kt = 0; kt < POOL_DIM; kt += KT) {
        __syncthreads();
        // pooled tile transposed into smem; global reads coalesced along k
        for (int idx = threadIdx.x; idx < GT * KT; idx += 512) {
            int r = idx >> 7, kk = idx & (KT - 1);
            sP[kk][r] = g_pooled[(size_t)(g0 + r) * POOL_DIM + kt + kk];
        }
        __syncthreads();

        const float* Wp = W + (size_t)kt * HIDDEN + j;
#pragma unroll 8
        for (int kk = 0; kk < KT; kk++) {
            float w = __ldg(Wp + (size_t)kk * HIDDEN);
            unsigned long long w2;
            asm("mov.b64 %0, {%1, %1};" : "=l"(w2) : "f"(w));
            const ulonglong2* p2 = (const ulonglong2*)&sP[kk][rg * 8];
            ulonglong2 pa = p2[0], pb = p2[1];
            asm("fma.rn.f32x2 %0, %1, %2, %0;" : "+l"(acc2[0]) : "l"(pa.x), "l"(w2));
            asm("fma.rn.f32x2 %0, %1, %2, %0;" : "+l"(acc2[1]) : "l"(pa.y), "l"(w2));
            asm("fma.rn.f32x2 %0, %1, %2, %0;" : "+l"(acc2[2]) : "l"(pb.x), "l"(w2));
            asm("fma.rn.f32x2 %0, %1, %2, %0;" : "+l"(acc2[3]) : "l"(pb.y), "l"(w2));
        }
    }

    float bj = bias[j];
#pragma unroll
    for (int r = 0; r < 4; r++) {
        float lo, hi;
        asm("mov.b64 {%0, %1}, %2;" : "=f"(lo), "=f"(hi) : "l"(acc2[r]));
        sH[rg * 8 + 2 * r][j]     = lo + bj;
        sH[rg * 8 + 2 * r + 1][j] = hi + bj;
    }
    __syncthreads();

    // LayerNorm + exact GELU: 16 warps, 2 rows each; lane covers 4 columns
    const int warp = threadIdx.x >> 5, lane = threadIdx.x & 31;
    for (int row = warp; row < GT; row += 16) {
        float v[4];
#pragma unroll
        for (int q = 0; q < 4; q++) v[q] = sH[row][lane + 32 * q];

        float s = v[0] + v[1] + v[2] + v[3];
#pragma unroll
        for (int o = 16; o > 0; o >>= 1) s += __shfl_xor_sync(0xffffffffu, s, o);
        float mu = s * (1.0f / 128.0f);

        float vs = 0.f;
#pragma unroll
        for (int q = 0; q < 4; q++) { float d = v[q] - mu; vs += d * d; }
#pragma unroll
        for (int o = 16; o > 0; o >>= 1) vs += __shfl_xor_sync(0xffffffffu, vs, o);
        float inv = rsqrtf(vs * (1.0f / 128.0f) + 1e-5f);

#pragma unroll
        for (int q = 0; q < 4; q++) {
            int col = lane + 32 * q;
            float y = (v[q] - mu) * inv * gamma[col] + beta[col];
            float ge = 0.5f * y * (1.0f + erff(y * 0.70710678118654752f));
            out[(size_t)(g0 + row) * HIDDEN + col] = ge;
        }
    }
}

// ---------------------------------------------------------------------------
extern "C" void kernel_launch(void* const* d_in, const int* in_sizes, int n_in,
                              void* d_out, int out_size) {
    int ix = -1;
    long long maxsz = -1;
    for (int i = 0; i < n_in; i++)
        if ((long long)in_sizes[i] > maxsz) { maxsz = in_sizes[i]; ix = i; }
    const int n_nodes = (int)(maxsz / HIDDEN);

    int ib = -1, iw = -1, vecs[3] = {-1, -1, -1}; int nv = 0;
    for (int i = 0; i < n_in; i++) {
        if (i == ix) continue;
        if (in_sizes[i] == n_nodes) ib = i;
        else if (in_sizes[i] == POOL_DIM * HIDDEN) iw = i;
        else if (in_sizes[i] == HIDDEN && nv < 3) vecs[nv++] = i;
    }

    const float* x     = (const float*)d_in[ix];
    const int*   batch = (const int*)d_in[ib];
    const float* W     = (const float*)d_in[iw];
    const float* b     = (const float*)d_in[vecs[0]];
    const float* gamma = (const float*)d_in[vecs[1]];
    const float* beta  = (const float*)d_in[vecs[2]];
    float* out = (float*)d_out;

    pool_kernel<<<NGRAPH, 512>>>(x, batch, n_nodes);
    gemm_ln_gelu_kernel<<<NGRAPH / 32, 512>>>(W, b, gamma, beta, out);
}

// round 4
// speedup vs baseline: 1.1346x; 1.1149x over previous
#include <cuda_runtime.h>
#include <math.h>

#define HIDDEN 128
#define NGRAPH 4096
#define POOL_DIM (3 * HIDDEN)

// Scratch for pooled features [NGRAPH, 3*HIDDEN] = 6 MB
__device__ float g_pooled[NGRAPH * POOL_DIM];

// ---------------------------------------------------------------------------
// Phase A: one block per graph (batch sorted -> contiguous range via binary
// search). 512 threads = 16 row-groups x 32 lanes; lane owns 4 channels via
// float4. Every iteration issues 4 independent loads (clamped + predicated):
// no serial MLP-1 tail.
// ---------------------------------------------------------------------------
__device__ __forceinline__ int batch_val(const int* __restrict__ w, int i, bool is64) {
    return is64 ? w[2 * i] : w[i];
}

__global__ void __launch_bounds__(512)
pool_kernel(const float* __restrict__ x, const int* __restrict__ batch_raw, int n_nodes) {
    const int g = blockIdx.x;
    __shared__ int s_range[2];

    // int64 vs int32 detection (little-endian, ids < 2^31)
    const bool is64 = (batch_raw[n_nodes - 1] == 0) && (batch_raw[n_nodes - 2] != 0);

    if (threadIdx.x == 0) {
        int lo = 0, hi = n_nodes;
        while (lo < hi) { int mid = (lo + hi) >> 1;
            if (batch_val(batch_raw, mid, is64) < g) lo = mid + 1; else hi = mid; }
        s_range[0] = lo;
    }
    if (threadIdx.x == 32) {
        int lo = 0, hi = n_nodes;
        while (lo < hi) { int mid = (lo + hi) >> 1;
            if (batch_val(batch_raw, mid, is64) < g + 1) lo = mid + 1; else hi = mid; }
        s_range[1] = lo;
    }
    __syncthreads();
    const int start = s_range[0];
    const int end   = s_range[1];

    const int lane = threadIdx.x & 31;
    const int h    = threadIdx.x >> 5;   // row group 0..15

    const float4* xv = (const float4*)x;   // 32 float4 per row

    const float NEG = -3.402823466e38f;
    float4 s0 = make_float4(0.f, 0.f, 0.f, 0.f), s1 = s0, s2 = s0, s3 = s0;
    float4 m0 = make_float4(NEG, NEG, NEG, NEG), m1 = m0, m2 = m0, m3 = m0;

    for (int i = start + h; i < end; i += 64) {
        const int i1 = i + 16, i2 = i + 32, i3 = i + 48;
        const float f1 = (i1 < end) ? 1.0f : 0.0f;
        const float f2 = (i2 < end) ? 1.0f : 0.0f;
        const float f3 = (i3 < end) ? 1.0f : 0.0f;
        // clamp to a valid row (i) when out of range: duplicate is harmless
        // for max; sum contribution is masked by f* below.
        const int c1 = (i1 < end) ? i1 : i;
        const int c2 = (i2 < end) ? i2 : i;
        const int c3 = (i3 < end) ? i3 : i;

        float4 v0 = __ldcs(xv + (size_t)i  * 32 + lane);
        float4 v1 = __ldcs(xv + (size_t)c1 * 32 + lane);
        float4 v2 = __ldcs(xv + (size_t)c2 * 32 + lane);
        float4 v3 = __ldcs(xv + (size_t)c3 * 32 + lane);

        s0.x += v0.x; s0.y += v0.y; s0.z += v0.z; s0.w += v0.w;
        m0.x = fmaxf(m0.x, v0.x); m0.y = fmaxf(m0.y, v0.y);
        m0.z = fmaxf(m0.z, v0.z); m0.w = fmaxf(m0.w, v0.w);

        s1.x = fmaf(v1.x, f1, s1.x); s1.y = fmaf(v1.y, f1, s1.y);
        s1.z = fmaf(v1.z, f1, s1.z); s1.w = fmaf(v1.w, f1, s1.w);
        m1.x = fmaxf(m1.x, v1.x); m1.y = fmaxf(m1.y, v1.y);
        m1.z = fmaxf(m1.z, v1.z); m1.w = fmaxf(m1.w, v1.w);

        s2.x = fmaf(v2.x, f2, s2.x); s2.y = fmaf(v2.y, f2, s2.y);
        s2.z = fmaf(v2.z, f2, s2.z); s2.w = fmaf(v2.w, f2, s2.w);
        m2.x = fmaxf(m2.x, v2.x); m2.y = fmaxf(m2.y, v2.y);
        m2.z = fmaxf(m2.z, v2.z); m2.w = fmaxf(m2.w, v2.w);

        s3.x = fmaf(v3.x, f3, s3.x); s3.y = fmaf(v3.y, f3, s3.y);
        s3.z = fmaf(v3.z, f3, s3.z); s3.w = fmaf(v3.w, f3, s3.w);
        m3.x = fmaxf(m3.x, v3.x); m3.y = fmaxf(m3.y, v3.y);
        m3.z = fmaxf(m3.z, v3.z); m3.w = fmaxf(m3.w, v3.w);
    }

    float4 S = make_float4(s0.x + s1.x + s2.x + s3.x, s0.y + s1.y + s2.y + s3.y,
                           s0.z + s1.z + s2.z + s3.z, s0.w + s1.w + s2.w + s3.w);
    float4 M = make_float4(fmaxf(fmaxf(m0.x, m1.x), fmaxf(m2.x, m3.x)),
                           fmaxf(fmaxf(m0.y, m1.y), fmaxf(m2.y, m3.y)),
                           fmaxf(fmaxf(m0.z, m1.z), fmaxf(m2.z, m3.z)),
                           fmaxf(fmaxf(m0.w, m1.w), fmaxf(m2.w, m3.w)));

    __shared__ float4 s_sum[16][32];
    __shared__ float4 s_max[16][32];
    s_sum[h][lane] = S;
    s_max[h][lane] = M;
    __syncthreads();

    if (threadIdx.x < 128) {
        const int part = threadIdx.x >> 5;
        const int l    = threadIdx.x & 31;
        float4 a = s_sum[part][l], b = s_sum[part + 4][l],
               c = s_sum[part + 8][l], d = s_sum[part + 12][l];
        s_sum[part][l] = make_float4(a.x + b.x + c.x + d.x, a.y + b.y + c.y + d.y,
                                     a.z + b.z + c.z + d.z, a.w + b.w + c.w + d.w);
        float4 am = s_max[part][l], bm = s_max[part + 4][l],
               cm = s_max[part + 8][l], dm = s_max[part + 12][l];
        s_max[part][l] = make_float4(fmaxf(fmaxf(am.x, bm.x), fmaxf(cm.x, dm.x)),
                                     fmaxf(fmaxf(am.y, bm.y), fmaxf(cm.y, dm.y)),
                                     fmaxf(fmaxf(am.z, bm.z), fmaxf(cm.z, dm.z)),
                                     fmaxf(fmaxf(am.w, bm.w), fmaxf(cm.w, dm.w)));
    }
    __syncthreads();

    if (threadIdx.x < 32) {
        const int l = threadIdx.x;
        float4 a = s_sum[0][l], b = s_sum[1][l], c = s_sum[2][l], d = s_sum[3][l];
        float4 SS = make_float4(a.x + b.x + c.x + d.x, a.y + b.y + c.y + d.y,
                                a.z + b.z + c.z + d.z, a.w + b.w + c.w + d.w);
        float4 am = s_max[0][l], bm = s_max[1][l], cm = s_max[2][l], dm = s_max[3][l];
        float4 MM = make_float4(fmaxf(fmaxf(am.x, bm.x), fmaxf(cm.x, dm.x)),
                                fmaxf(fmaxf(am.y, bm.y), fmaxf(cm.y, dm.y)),
                                fmaxf(fmaxf(am.z, bm.z), fmaxf(cm.z, dm.z)),
                                fmaxf(fmaxf(am.w, bm.w), fmaxf(cm.w, dm.w)));
        const int cnt = end - start;
        const float inv = 1.0f / fmaxf((float)cnt, 1.0f);
        float4 mean = make_float4(SS.x * inv, SS.y * inv, SS.z * inv, SS.w * inv);
        if (cnt <= 0) MM = make_float4(0.f, 0.f, 0.f, 0.f);
        float4* o = (float4*)(g_pooled + (size_t)g * POOL_DIM);
        o[l]      = mean;
        o[32 + l] = MM;
        o[64 + l] = SS;
    }
}

// ---------------------------------------------------------------------------
// Phase B: fused GEMM [4096,384]x[384,128] + bias + LayerNorm + exact GELU.
// W via __ldg (192 KB, L1-resident). Pooled tile transposed in smem; each
// thread's 8 rows = two uniform LDS.128 broadcasts. MANUAL distance-2
// software pipeline: iteration n's loads feed iteration n+1's packed f32x2
// FMAs, so LDS/LDG latency is hidden by issue instead of occupancy.
// ---------------------------------------------------------------------------
#define FMA4(wv, pa, pb)                                                        \
    do {                                                                        \
        unsigned long long w2_;                                                 \
        asm("mov.b64 %0, {%1, %1};" : "=l"(w2_) : "f"(wv));                     \
        asm("fma.rn.f32x2 %0, %1, %2, %0;" : "+l"(acc2[0]) : "l"((pa).x), "l"(w2_)); \
        asm("fma.rn.f32x2 %0, %1, %2, %0;" : "+l"(acc2[1]) : "l"((pa).y), "l"(w2_)); \
        asm("fma.rn.f32x2 %0, %1, %2, %0;" : "+l"(acc2[2]) : "l"((pb).x), "l"(w2_)); \
        asm("fma.rn.f32x2 %0, %1, %2, %0;" : "+l"(acc2[3]) : "l"((pb).y), "l"(w2_)); \
    } while (0)

__global__ void __launch_bounds__(512)
gemm_ln_gelu_kernel(const float* __restrict__ W, const float* __restrict__ bias,
                    const float* __restrict__ gamma, const float* __restrict__ beta,
                    float* __restrict__ out) {
    const int GT = 32;    // graph rows per block
    const int KT = 128;   // k tile

    __shared__ float sP[KT][GT + 4];      // [kk][row], stride 36 floats (16B mult)
    __shared__ float sH[GT][HIDDEN + 4];  // post-GEMM h for LN

    const int g0 = blockIdx.x * GT;
    const int j  = threadIdx.x & (HIDDEN - 1);  // output column
    const int rg = threadIdx.x >> 7;            // 0..3: rows [rg*8, rg*8+8)

    unsigned long long acc2[4];
#pragma unroll
    for (int r = 0; r < 4; r++) acc2[r] = 0ull;

    for (int kt = 0; kt < POOL_DIM; kt += KT) {
        __syncthreads();
        for (int idx = threadIdx.x; idx < GT * KT; idx += 512) {
            int r = idx >> 7, kk = idx & (KT - 1);
            sP[kk][r] = g_pooled[(size_t)(g0 + r) * POOL_DIM + kt + kk];
        }
        __syncthreads();

        const float* Wp = W + (size_t)kt * HIDDEN + j;

        // prologue: stages for k=0,1
        float w0 = __ldg(Wp);
        float w1 = __ldg(Wp + HIDDEN);
        ulonglong2 a0 = ((const ulonglong2*)&sP[0][rg * 8])[0];
        ulonglong2 b0 = ((const ulonglong2*)&sP[0][rg * 8])[1];
        ulonglong2 a1 = ((const ulonglong2*)&sP[1][rg * 8])[0];
        ulonglong2 b1 = ((const ulonglong2*)&sP[1][rg * 8])[1];

#pragma unroll 4
        for (int kk = 0; kk < KT - 2; kk += 2) {
            float wn0 = __ldg(Wp + (size_t)(kk + 2) * HIDDEN);
            ulonglong2 an0 = ((const ulonglong2*)&sP[kk + 2][rg * 8])[0];
            ulonglong2 bn0 = ((const ulonglong2*)&sP[kk + 2][rg * 8])[1];
            FMA4(w0, a0, b0);
            float wn1 = __ldg(Wp + (size_t)(kk + 3) * HIDDEN);
            ulonglong2 an1 = ((const ulonglong2*)&sP[kk + 3][rg * 8])[0];
            ulonglong2 bn1 = ((const ulonglong2*)&sP[kk + 3][rg * 8])[1];
            FMA4(w1, a1, b1);
            w0 = wn0; a0 = an0; b0 = bn0;
            w1 = wn1; a1 = an1; b1 = bn1;
        }
        FMA4(w0, a0, b0);
        FMA4(w1, a1, b1);
    }

    float bj = bias[j];
#pragma unroll
    for (int r = 0; r < 4; r++) {
        float lo, hi;
        asm("mov.b64 {%0, %1}, %2;" : "=f"(lo), "=f"(hi) : "l"(acc2[r]));
        sH[rg * 8 + 2 * r][j]     = lo + bj;
        sH[rg * 8 + 2 * r + 1][j] = hi + bj;
    }
    __syncthreads();

    // LayerNorm + exact GELU: 16 warps, 2 rows each; lane covers 4 columns
    const int warp = threadIdx.x >> 5, lane = threadIdx.x & 31;
    for (int row = warp; row < GT; row += 16) {
        float v[4];
#pragma unroll
        for (int q = 0; q < 4; q++) v[q] = sH[row][lane + 32 * q];

        float s = v[0] + v[1] + v[2] + v[3];
#pragma unroll
        for (int o = 16; o > 0; o >>= 1) s += __shfl_xor_sync(0xffffffffu, s, o);
        float mu = s * (1.0f / 128.0f);

        float vs = 0.f;
#pragma unroll
        for (int q = 0; q < 4; q++) { float d = v[q] - mu; vs += d * d; }
#pragma unroll
        for (int o = 16; o > 0; o >>= 1) vs += __shfl_xor_sync(0xffffffffu, vs, o);
        float inv = rsqrtf(vs * (1.0f / 128.0f) + 1e-5f);

#pragma unroll
        for (int q = 0; q < 4; q++) {
            int col = lane + 32 * q;
            float y = (v[q] - mu) * inv * gamma[col] + beta[col];
            float ge = 0.5f * y * (1.0f + erff(y * 0.70710678118654752f));
            out[(size_t)(g0 + row) * HIDDEN + col] = ge;
        }
    }
}

// ---------------------------------------------------------------------------
extern "C" void kernel_launch(void* const* d_in, const int* in_sizes, int n_in,
                              void* d_out, int out_size) {
    int ix = -1;
    long long maxsz = -1;
    for (int i = 0; i < n_in; i++)
        if ((long long)in_sizes[i] > maxsz) { maxsz = in_sizes[i]; ix = i; }
    const int n_nodes = (int)(maxsz / HIDDEN);

    int ib = -1, iw = -1, vecs[3] = {-1, -1, -1}; int nv = 0;
    for (int i = 0; i < n_in; i++) {
        if (i == ix) continue;
        if (in_sizes[i] == n_nodes) ib = i;
        else if (in_sizes[i] == POOL_DIM * HIDDEN) iw = i;
        else if (in_sizes[i] == HIDDEN && nv < 3) vecs[nv++] = i;
    }

    const float* x     = (const float*)d_in[ix];
    const int*   batch = (const int*)d_in[ib];
    const float* W     = (const float*)d_in[iw];
    const float* b     = (const float*)d_in[vecs[0]];
    const float* gamma = (const float*)d_in[vecs[1]];
    const float* beta  = (const float*)d_in[vecs[2]];
    float* out = (float*)d_out;

    pool_kernel<<<NGRAPH, 512>>>(x, batch, n_nodes);
    gemm_ln_gelu_kernel<<<NGRAPH / 32, 512>>>(W, b, gamma, beta, out);
}

// round 5
// speedup vs baseline: 1.1517x; 1.0151x over previous
#include <cuda_runtime.h>
#include <math.h>

#define HIDDEN 128
#define NGRAPH 4096
#define POOL_DIM (3 * HIDDEN)

// Scratch for pooled features [NGRAPH, 3*HIDDEN] = 6 MB
__device__ float g_pooled[NGRAPH * POOL_DIM];

// ---------------------------------------------------------------------------
// Phase A: one block per graph (batch sorted -> contiguous range via binary
// search). 512 threads = 16 row-groups x 32 lanes; lane owns 4 channels via
// float4. Every iteration issues 4 independent loads (clamped + predicated).
// ---------------------------------------------------------------------------
__device__ __forceinline__ int batch_val(const int* __restrict__ w, int i, bool is64) {
    return is64 ? w[2 * i] : w[i];
}

__global__ void __launch_bounds__(512)
pool_kernel(const float* __restrict__ x, const int* __restrict__ batch_raw, int n_nodes) {
    const int g = blockIdx.x;
    __shared__ int s_range[2];

    const bool is64 = (batch_raw[n_nodes - 1] == 0) && (batch_raw[n_nodes - 2] != 0);

    if (threadIdx.x == 0) {
        int lo = 0, hi = n_nodes;
        while (lo < hi) { int mid = (lo + hi) >> 1;
            if (batch_val(batch_raw, mid, is64) < g) lo = mid + 1; else hi = mid; }
        s_range[0] = lo;
    }
    if (threadIdx.x == 32) {
        int lo = 0, hi = n_nodes;
        while (lo < hi) { int mid = (lo + hi) >> 1;
            if (batch_val(batch_raw, mid, is64) < g + 1) lo = mid + 1; else hi = mid; }
        s_range[1] = lo;
    }
    __syncthreads();
    const int start = s_range[0];
    const int end   = s_range[1];

    const int lane = threadIdx.x & 31;
    const int h    = threadIdx.x >> 5;   // row group 0..15

    const float4* xv = (const float4*)x;

    const float NEG = -3.402823466e38f;
    float4 s0 = make_float4(0.f, 0.f, 0.f, 0.f), s1 = s0, s2 = s0, s3 = s0;
    float4 m0 = make_float4(NEG, NEG, NEG, NEG), m1 = m0, m2 = m0, m3 = m0;

    for (int i = start + h; i < end; i += 64) {
        const int i1 = i + 16, i2 = i + 32, i3 = i + 48;
        const float f1 = (i1 < end) ? 1.0f : 0.0f;
        const float f2 = (i2 < end) ? 1.0f : 0.0f;
        const float f3 = (i3 < end) ? 1.0f : 0.0f;
        const int c1 = (i1 < end) ? i1 : i;
        const int c2 = (i2 < end) ? i2 : i;
        const int c3 = (i3 < end) ? i3 : i;

        float4 v0 = __ldcs(xv + (size_t)i  * 32 + lane);
        float4 v1 = __ldcs(xv + (size_t)c1 * 32 + lane);
        float4 v2 = __ldcs(xv + (size_t)c2 * 32 + lane);
        float4 v3 = __ldcs(xv + (size_t)c3 * 32 + lane);

        s0.x += v0.x; s0.y += v0.y; s0.z += v0.z; s0.w += v0.w;
        m0.x = fmaxf(m0.x, v0.x); m0.y = fmaxf(m0.y, v0.y);
        m0.z = fmaxf(m0.z, v0.z); m0.w = fmaxf(m0.w, v0.w);

        s1.x = fmaf(v1.x, f1, s1.x); s1.y = fmaf(v1.y, f1, s1.y);
        s1.z = fmaf(v1.z, f1, s1.z); s1.w = fmaf(v1.w, f1, s1.w);
        m1.x = fmaxf(m1.x, v1.x); m1.y = fmaxf(m1.y, v1.y);
        m1.z = fmaxf(m1.z, v1.z); m1.w = fmaxf(m1.w, v1.w);

        s2.x = fmaf(v2.x, f2, s2.x); s2.y = fmaf(v2.y, f2, s2.y);
        s2.z = fmaf(v2.z, f2, s2.z); s2.w = fmaf(v2.w, f2, s2.w);
        m2.x = fmaxf(m2.x, v2.x); m2.y = fmaxf(m2.y, v2.y);
        m2.z = fmaxf(m2.z, v2.z); m2.w = fmaxf(m2.w, v2.w);

        s3.x = fmaf(v3.x, f3, s3.x); s3.y = fmaf(v3.y, f3, s3.y);
        s3.z = fmaf(v3.z, f3, s3.z); s3.w = fmaf(v3.w, f3, s3.w);
        m3.x = fmaxf(m3.x, v3.x); m3.y = fmaxf(m3.y, v3.y);
        m3.z = fmaxf(m3.z, v3.z); m3.w = fmaxf(m3.w, v3.w);
    }

    float4 S = make_float4(s0.x + s1.x + s2.x + s3.x, s0.y + s1.y + s2.y + s3.y,
                           s0.z + s1.z + s2.z + s3.z, s0.w + s1.w + s2.w + s3.w);
    float4 M = make_float4(fmaxf(fmaxf(m0.x, m1.x), fmaxf(m2.x, m3.x)),
                           fmaxf(fmaxf(m0.y, m1.y), fmaxf(m2.y, m3.y)),
                           fmaxf(fmaxf(m0.z, m1.z), fmaxf(m2.z, m3.z)),
                           fmaxf(fmaxf(m0.w, m1.w), fmaxf(m2.w, m3.w)));

    __shared__ float4 s_sum[16][32];
    __shared__ float4 s_max[16][32];
    s_sum[h][lane] = S;
    s_max[h][lane] = M;
    __syncthreads();

    if (threadIdx.x < 128) {
        const int part = threadIdx.x >> 5;
        const int l    = threadIdx.x & 31;
        float4 a = s_sum[part][l], b = s_sum[part + 4][l],
               c = s_sum[part + 8][l], d = s_sum[part + 12][l];
        s_sum[part][l] = make_float4(a.x + b.x + c.x + d.x, a.y + b.y + c.y + d.y,
                                     a.z + b.z + c.z + d.z, a.w + b.w + c.w + d.w);
        float4 am = s_max[part][l], bm = s_max[part + 4][l],
               cm = s_max[part + 8][l], dm = s_max[part + 12][l];
        s_max[part][l] = make_float4(fmaxf(fmaxf(am.x, bm.x), fmaxf(cm.x, dm.x)),
                                     fmaxf(fmaxf(am.y, bm.y), fmaxf(cm.y, dm.y)),
                                     fmaxf(fmaxf(am.z, bm.z), fmaxf(cm.z, dm.z)),
                                     fmaxf(fmaxf(am.w, bm.w), fmaxf(cm.w, dm.w)));
    }
    __syncthreads();

    if (threadIdx.x < 32) {
        const int l = threadIdx.x;
        float4 a = s_sum[0][l], b = s_sum[1][l], c = s_sum[2][l], d = s_sum[3][l];
        float4 SS = make_float4(a.x + b.x + c.x + d.x, a.y + b.y + c.y + d.y,
                                a.z + b.z + c.z + d.z, a.w + b.w + c.w + d.w);
        float4 am = s_max[0][l], bm = s_max[1][l], cm = s_max[2][l], dm = s_max[3][l];
        float4 MM = make_float4(fmaxf(fmaxf(am.x, bm.x), fmaxf(cm.x, dm.x)),
                                fmaxf(fmaxf(am.y, bm.y), fmaxf(cm.y, dm.y)),
                                fmaxf(fmaxf(am.z, bm.z), fmaxf(cm.z, dm.z)),
                                fmaxf(fmaxf(am.w, bm.w), fmaxf(cm.w, dm.w)));
        const int cnt = end - start;
        const float inv = 1.0f / fmaxf((float)cnt, 1.0f);
        float4 mean = make_float4(SS.x * inv, SS.y * inv, SS.z * inv, SS.w * inv);
        if (cnt <= 0) MM = make_float4(0.f, 0.f, 0.f, 0.f);
        float4* o = (float4*)(g_pooled + (size_t)g * POOL_DIM);
        o[l]      = mean;
        o[32 + l] = MM;
        o[64 + l] = SS;
    }
}

// ---------------------------------------------------------------------------
// Phase B: fused GEMM [4096,384]x[384,128] + bias + LayerNorm + exact GELU.
// BOTH operands staged in smem (W tile 32 KB + transposed pooled tile), and
// the inner loop is a distance-2 software pipeline of pure LDS (29-cyc lat,
// fully covered). sH aliases sW's smem (dead after main loop) to fit 48 KB.
// ---------------------------------------------------------------------------
#define FMA4(wv, pa, pb)                                                        \
    do {                                                                        \
        unsigned long long w2_;                                                 \
        asm("mov.b64 %0, {%1, %1};" : "=l"(w2_) : "f"(wv));                     \
        asm("fma.rn.f32x2 %0, %1, %2, %0;" : "+l"(acc2[0]) : "l"((pa).x), "l"(w2_)); \
        asm("fma.rn.f32x2 %0, %1, %2, %0;" : "+l"(acc2[1]) : "l"((pa).y), "l"(w2_)); \
        asm("fma.rn.f32x2 %0, %1, %2, %0;" : "+l"(acc2[2]) : "l"((pb).x), "l"(w2_)); \
        asm("fma.rn.f32x2 %0, %1, %2, %0;" : "+l"(acc2[3]) : "l"((pb).y), "l"(w2_)); \
    } while (0)

__global__ void __launch_bounds__(512)
gemm_ln_gelu_kernel(const float* __restrict__ W, const float* __restrict__ bias,
                    const float* __restrict__ gamma, const float* __restrict__ beta,
                    float* __restrict__ out) {
    const int GT = 32;   // graph rows per block
    const int KT = 64;   // k tile

    // 41984 bytes: sW [64][128] at 0, sP [64][36] at 32768; sH aliases sW.
    __shared__ __align__(16) char smem_buf[KT * HIDDEN * 4 + KT * (GT + 4) * 4];
    float (*sW)[HIDDEN]     = (float(*)[HIDDEN])smem_buf;
    float (*sP)[GT + 4]     = (float(*)[GT + 4])(smem_buf + KT * HIDDEN * 4);
    float (*sH)[HIDDEN + 4] = (float(*)[HIDDEN + 4])smem_buf;  // after main loop

    const int g0 = blockIdx.x * GT;
    const int j  = threadIdx.x & (HIDDEN - 1);  // output column
    const int rg = threadIdx.x >> 7;            // 0..3: rows [rg*8, rg*8+8)

    unsigned long long acc2[4];
#pragma unroll
    for (int r = 0; r < 4; r++) acc2[r] = 0ull;

    for (int kt = 0; kt < POOL_DIM; kt += KT) {
        __syncthreads();
        // W tile: float4-coalesced, same layout as global
        {
            const float4* Wv = (const float4*)(W + (size_t)kt * HIDDEN);
            float4* sWv = (float4*)sW;
#pragma unroll
            for (int idx = threadIdx.x; idx < KT * (HIDDEN / 4); idx += 512)
                sWv[idx] = Wv[idx];
        }
        // pooled tile transposed; global reads coalesced along k
#pragma unroll
        for (int idx = threadIdx.x; idx < GT * KT; idx += 512) {
            int r = idx >> 6, kk = idx & (KT - 1);
            sP[kk][r] = g_pooled[(size_t)(g0 + r) * POOL_DIM + kt + kk];
        }
        __syncthreads();

        // distance-2 software pipeline over k (all LDS)
        float w0 = sW[0][j];
        float w1 = sW[1][j];
        ulonglong2 a0 = ((const ulonglong2*)&sP[0][rg * 8])[0];
        ulonglong2 b0 = ((const ulonglong2*)&sP[0][rg * 8])[1];
        ulonglong2 a1 = ((const ulonglong2*)&sP[1][rg * 8])[0];
        ulonglong2 b1 = ((const ulonglong2*)&sP[1][rg * 8])[1];

#pragma unroll 4
        for (int kk = 0; kk < KT - 2; kk += 2) {
            float wn0 = sW[kk + 2][j];
            ulonglong2 an0 = ((const ulonglong2*)&sP[kk + 2][rg * 8])[0];
            ulonglong2 bn0 = ((const ulonglong2*)&sP[kk + 2][rg * 8])[1];
            FMA4(w0, a0, b0);
            float wn1 = sW[kk + 3][j];
            ulonglong2 an1 = ((const ulonglong2*)&sP[kk + 3][rg * 8])[0];
            ulonglong2 bn1 = ((const ulonglong2*)&sP[kk + 3][rg * 8])[1];
            FMA4(w1, a1, b1);
            w0 = wn0; a0 = an0; b0 = bn0;
            w1 = wn1; a1 = an1; b1 = bn1;
        }
        FMA4(w0, a0, b0);
        FMA4(w1, a1, b1);
    }

    __syncthreads();   // sW reads done before sH alias writes

    float bj = bias[j];
#pragma unroll
    for (int r = 0; r < 4; r++) {
        float lo, hi;
        asm("mov.b64 {%0, %1}, %2;" : "=f"(lo), "=f"(hi) : "l"(acc2[r]));
        sH[rg * 8 + 2 * r][j]     = lo + bj;
        sH[rg * 8 + 2 * r + 1][j] = hi + bj;
    }
    __syncthreads();

    // LayerNorm + exact GELU: 16 warps, 2 rows each; lane covers 4 columns
    const int warp = threadIdx.x >> 5, lane = threadIdx.x & 31;
    for (int row = warp; row < GT; row += 16) {
        float v[4];
#pragma unroll
        for (int q = 0; q < 4; q++) v[q] = sH[row][lane + 32 * q];

        float s = v[0] + v[1] + v[2] + v[3];
#pragma unroll
        for (int o = 16; o > 0; o >>= 1) s += __shfl_xor_sync(0xffffffffu, s, o);
        float mu = s * (1.0f / 128.0f);

        float vs = 0.f;
#pragma unroll
        for (int q = 0; q < 4; q++) { float d = v[q] - mu; vs += d * d; }
#pragma unroll
        for (int o = 16; o > 0; o >>= 1) vs += __shfl_xor_sync(0xffffffffu, vs, o);
        float inv = rsqrtf(vs * (1.0f / 128.0f) + 1e-5f);

#pragma unroll
        for (int q = 0; q < 4; q++) {
            int col = lane + 32 * q;
            float y = (v[q] - mu) * inv * gamma[col] + beta[col];
            float ge = 0.5f * y * (1.0f + erff(y * 0.70710678118654752f));
            out[(size_t)(g0 + row) * HIDDEN + col] = ge;
        }
    }
}

// ---------------------------------------------------------------------------
extern "C" void kernel_launch(void* const* d_in, const int* in_sizes, int n_in,
                              void* d_out, int out_size) {
    int ix = -1;
    long long maxsz = -1;
    for (int i = 0; i < n_in; i++)
        if ((long long)in_sizes[i] > maxsz) { maxsz = in_sizes[i]; ix = i; }
    const int n_nodes = (int)(maxsz / HIDDEN);

    int ib = -1, iw = -1, vecs[3] = {-1, -1, -1}; int nv = 0;
    for (int i = 0; i < n_in; i++) {
        if (i == ix) continue;
        if (in_sizes[i] == n_nodes) ib = i;
        else if (in_sizes[i] == POOL_DIM * HIDDEN) iw = i;
        else if (in_sizes[i] == HIDDEN && nv < 3) vecs[nv++] = i;
    }

    const float* x     = (const float*)d_in[ix];
    const int*   batch = (const int*)d_in[ib];
    const float* W     = (const float*)d_in[iw];
    const float* b     = (const float*)d_in[vecs[0]];
    const float* gamma = (const float*)d_in[vecs[1]];
    const float* beta  = (const float*)d_in[vecs[2]];
    float* out = (float*)d_out;

    pool_kernel<<<NGRAPH, 512>>>(x, batch, n_nodes);
    gemm_ln_gelu_kernel<<<NGRAPH / 32, 512>>>(W, b, gamma, beta, out);
}

// round 6
// speedup vs baseline: 1.4045x; 1.2195x over previous
#include <cuda_runtime.h>
#include <math.h>

#define HIDDEN 128
#define NGRAPH 4096
#define POOL_DIM (3 * HIDDEN)

__device__ float g_pooled[NGRAPH * POOL_DIM];   // 6 MB scratch
__device__ int   g_seg[NGRAPH + 1];             // segment starts (+sentinel)

__device__ __forceinline__ int batch_val(const int* __restrict__ w, int i, bool is64) {
    return is64 ? w[2 * i] : w[i];
}

// ---------------------------------------------------------------------------
// Phase 0: one linear pass over batch -> segment boundaries for all graphs.
// start[g] = first i with batch[i] >= g; empty graphs handled by the gap loop.
// ---------------------------------------------------------------------------
__global__ void seg_kernel(const int* __restrict__ batch_raw, int n_nodes) {
    const bool is64 = (batch_raw[n_nodes - 1] == 0) && (batch_raw[n_nodes - 2] != 0);
    int i = blockIdx.x * blockDim.x + threadIdx.x;
    if (i >= n_nodes) return;
    int bi = batch_val(batch_raw, i, is64);
    if (i == 0) {
        for (int g = 0; g <= bi; g++) g_seg[g] = 0;
    } else {
        int bp = batch_val(batch_raw, i - 1, is64);
        for (int g = bp + 1; g <= bi; g++) g_seg[g] = i;
    }
    if (i == n_nodes - 1) {
        for (int g = bi + 1; g <= NGRAPH; g++) g_seg[g] = n_nodes;
    }
}

// ---------------------------------------------------------------------------
// Phase A: one block per graph. Bounds come from g_seg (no binary search, no
// startup barrier). 512 threads = 16 row-groups x 32 lanes; lane owns 4
// channels via float4. Main loop: 4 unpredicated independent 512B loads;
// single predicated tail iteration.
// ---------------------------------------------------------------------------
__global__ void __launch_bounds__(512)
pool_kernel(const float* __restrict__ x) {
    const int g     = blockIdx.x;
    const int start = g_seg[g];
    const int end   = g_seg[g + 1];

    const int lane = threadIdx.x & 31;
    const int h    = threadIdx.x >> 5;   // row group 0..15

    const float4* xv = (const float4*)x;

    const float NEG = -3.402823466e38f;
    float4 s0 = make_float4(0.f, 0.f, 0.f, 0.f), s1 = s0, s2 = s0, s3 = s0;
    float4 m0 = make_float4(NEG, NEG, NEG, NEG), m1 = m0, m2 = m0, m3 = m0;

    int i = start + h;
    for (; i + 48 < end; i += 64) {
        float4 v0 = __ldcs(xv + (size_t)i * 32 + lane);
        float4 v1 = __ldcs(xv + (size_t)(i + 16) * 32 + lane);
        float4 v2 = __ldcs(xv + (size_t)(i + 32) * 32 + lane);
        float4 v3 = __ldcs(xv + (size_t)(i + 48) * 32 + lane);
        s0.x += v0.x; s0.y += v0.y; s0.z += v0.z; s0.w += v0.w;
        m0.x = fmaxf(m0.x, v0.x); m0.y = fmaxf(m0.y, v0.y);
        m0.z = fmaxf(m0.z, v0.z); m0.w = fmaxf(m0.w, v0.w);
        s1.x += v1.x; s1.y += v1.y; s1.z += v1.z; s1.w += v1.w;
        m1.x = fmaxf(m1.x, v1.x); m1.y = fmaxf(m1.y, v1.y);
        m1.z = fmaxf(m1.z, v1.z); m1.w = fmaxf(m1.w, v1.w);
        s2.x += v2.x; s2.y += v2.y; s2.z += v2.z; s2.w += v2.w;
        m2.x = fmaxf(m2.x, v2.x); m2.y = fmaxf(m2.y, v2.y);
        m2.z = fmaxf(m2.z, v2.z); m2.w = fmaxf(m2.w, v2.w);
        s3.x += v3.x; s3.y += v3.y; s3.z += v3.z; s3.w += v3.w;
        m3.x = fmaxf(m3.x, v3.x); m3.y = fmaxf(m3.y, v3.y);
        m3.z = fmaxf(m3.z, v3.z); m3.w = fmaxf(m3.w, v3.w);
    }
    if (i < end) {
        const int i1 = i + 16, i2 = i + 32;
        const float f1 = (i1 < end) ? 1.0f : 0.0f;
        const float f2 = (i2 < end) ? 1.0f : 0.0f;
        const int c1 = (i1 < end) ? i1 : i;   // clamp: dup is harmless for max,
        const int c2 = (i2 < end) ? i2 : i;   // sum masked by f*
        float4 v0 = __ldcs(xv + (size_t)i  * 32 + lane);
        float4 v1 = __ldcs(xv + (size_t)c1 * 32 + lane);
        float4 v2 = __ldcs(xv + (size_t)c2 * 32 + lane);
        s0.x += v0.x; s0.y += v0.y; s0.z += v0.z; s0.w += v0.w;
        m0.x = fmaxf(m0.x, v0.x); m0.y = fmaxf(m0.y, v0.y);
        m0.z = fmaxf(m0.z, v0.z); m0.w = fmaxf(m0.w, v0.w);
        s1.x = fmaf(v1.x, f1, s1.x); s1.y = fmaf(v1.y, f1, s1.y);
        s1.z = fmaf(v1.z, f1, s1.z); s1.w = fmaf(v1.w, f1, s1.w);
        m1.x = fmaxf(m1.x, v1.x); m1.y = fmaxf(m1.y, v1.y);
        m1.z = fmaxf(m1.z, v1.z); m1.w = fmaxf(m1.w, v1.w);
        s2.x = fmaf(v2.x, f2, s2.x); s2.y = fmaf(v2.y, f2, s2.y);
        s2.z = fmaf(v2.z, f2, s2.z); s2.w = fmaf(v2.w, f2, s2.w);
        m2.x = fmaxf(m2.x, v2.x); m2.y = fmaxf(m2.y, v2.y);
        m2.z = fmaxf(m2.z, v2.z); m2.w = fmaxf(m2.w, v2.w);
    }

    float4 S = make_float4(s0.x + s1.x + s2.x + s3.x, s0.y + s1.y + s2.y + s3.y,
                           s0.z + s1.z + s2.z + s3.z, s0.w + s1.w + s2.w + s3.w);
    float4 M = make_float4(fmaxf(fmaxf(m0.x, m1.x), fmaxf(m2.x, m3.x)),
                           fmaxf(fmaxf(m0.y, m1.y), fmaxf(m2.y, m3.y)),
                           fmaxf(fmaxf(m0.z, m1.z), fmaxf(m2.z, m3.z)),
                           fmaxf(fmaxf(m0.w, m1.w), fmaxf(m2.w, m3.w)));

    __shared__ float4 s_sum[16][32];
    __shared__ float4 s_max[16][32];
    s_sum[h][lane] = S;
    s_max[h][lane] = M;
    __syncthreads();

    if (threadIdx.x < 128) {
        const int part = threadIdx.x >> 5;
        const int l    = threadIdx.x & 31;
        float4 a = s_sum[part][l], b = s_sum[part + 4][l],
               c = s_sum[part + 8][l], d = s_sum[part + 12][l];
        s_sum[part][l] = make_float4(a.x + b.x + c.x + d.x, a.y + b.y + c.y + d.y,
                                     a.z + b.z + c.z + d.z, a.w + b.w + c.w + d.w);
        float4 am = s_max[part][l], bm = s_max[part + 4][l],
               cm = s_max[part + 8][l], dm = s_max[part + 12][l];
        s_max[part][l] = make_float4(fmaxf(fmaxf(am.x, bm.x), fmaxf(cm.x, dm.x)),
                                     fmaxf(fmaxf(am.y, bm.y), fmaxf(cm.y, dm.y)),
                                     fmaxf(fmaxf(am.z, bm.z), fmaxf(cm.z, dm.z)),
                                     fmaxf(fmaxf(am.w, bm.w), fmaxf(cm.w, dm.w)));
    }
    __syncthreads();

    if (threadIdx.x < 32) {
        const int l = threadIdx.x;
        float4 a = s_sum[0][l], b = s_sum[1][l], c = s_sum[2][l], d = s_sum[3][l];
        float4 SS = make_float4(a.x + b.x + c.x + d.x, a.y + b.y + c.y + d.y,
                                a.z + b.z + c.z + d.z, a.w + b.w + c.w + d.w);
        float4 am = s_max[0][l], bm = s_max[1][l], cm = s_max[2][l], dm = s_max[3][l];
        float4 MM = make_float4(fmaxf(fmaxf(am.x, bm.x), fmaxf(cm.x, dm.x)),
                                fmaxf(fmaxf(am.y, bm.y), fmaxf(cm.y, dm.y)),
                                fmaxf(fmaxf(am.z, bm.z), fmaxf(cm.z, dm.z)),
                                fmaxf(fmaxf(am.w, bm.w), fmaxf(cm.w, dm.w)));
        const int cnt = end - start;
        const float inv = 1.0f / fmaxf((float)cnt, 1.0f);
        float4 mean = make_float4(SS.x * inv, SS.y * inv, SS.z * inv, SS.w * inv);
        if (cnt <= 0) MM = make_float4(0.f, 0.f, 0.f, 0.f);
        float4* o = (float4*)(g_pooled + (size_t)g * POOL_DIM);
        o[l]      = mean;
        o[32 + l] = MM;
        o[64 + l] = SS;
    }
}

// ---------------------------------------------------------------------------
// Phase B: fused GEMM [4096,384]x[384,128] + bias + LayerNorm + exact GELU.
// GT=16 -> grid=256 (all 148 SMs busy, mostly 2 blocks/SM = 32 warps/SM).
// Both operands in smem, distance-2 pipelined pure-LDS inner loop,
// packed f32x2 FMAs. sH aliases sW.
// ---------------------------------------------------------------------------
#define FMA2P(wv, pa)                                                           \
    do {                                                                        \
        unsigned long long w2_;                                                 \
        asm("mov.b64 %0, {%1, %1};" : "=l"(w2_) : "f"(wv));                     \
        asm("fma.rn.f32x2 %0, %1, %2, %0;" : "+l"(acc2[0]) : "l"((pa).x), "l"(w2_)); \
        asm("fma.rn.f32x2 %0, %1, %2, %0;" : "+l"(acc2[1]) : "l"((pa).y), "l"(w2_)); \
    } while (0)

__global__ void __launch_bounds__(512)
gemm_ln_gelu_kernel(const float* __restrict__ W, const float* __restrict__ bias,
                    const float* __restrict__ gamma, const float* __restrict__ beta,
                    float* __restrict__ out) {
    const int GT = 16;   // graph rows per block
    const int KT = 64;   // k tile

    // sW [64][128] 32 KB at 0; sP [64][20] 5 KB after; sH aliases sW.
    __shared__ __align__(16) char smem_buf[KT * HIDDEN * 4 + KT * (GT + 4) * 4];
    float (*sW)[HIDDEN]     = (float(*)[HIDDEN])smem_buf;
    float (*sP)[GT + 4]     = (float(*)[GT + 4])(smem_buf + KT * HIDDEN * 4);
    float (*sH)[HIDDEN + 4] = (float(*)[HIDDEN + 4])smem_buf;

    const int g0 = blockIdx.x * GT;
    const int j  = threadIdx.x & (HIDDEN - 1);  // output column
    const int rg = threadIdx.x >> 7;            // 0..3: rows [rg*4, rg*4+4)

    unsigned long long acc2[2] = {0ull, 0ull};

    for (int kt = 0; kt < POOL_DIM; kt += KT) {
        __syncthreads();
        {
            const float4* Wv = (const float4*)(W + (size_t)kt * HIDDEN);
            float4* sWv = (float4*)sW;
#pragma unroll
            for (int idx = threadIdx.x; idx < KT * (HIDDEN / 4); idx += 512)
                sWv[idx] = Wv[idx];
        }
#pragma unroll
        for (int idx = threadIdx.x; idx < GT * KT; idx += 512) {
            int r = idx >> 6, kk = idx & (KT - 1);
            sP[kk][r] = g_pooled[(size_t)(g0 + r) * POOL_DIM + kt + kk];
        }
        __syncthreads();

        float w0 = sW[0][j];
        float w1 = sW[1][j];
        ulonglong2 a0 = *(const ulonglong2*)&sP[0][rg * 4];
        ulonglong2 a1 = *(const ulonglong2*)&sP[1][rg * 4];

#pragma unroll 8
        for (int kk = 0; kk < KT - 2; kk += 2) {
            float wn0 = sW[kk + 2][j];
            ulonglong2 an0 = *(const ulonglong2*)&sP[kk + 2][rg * 4];
            FMA2P(w0, a0);
            float wn1 = sW[kk + 3][j];
            ulonglong2 an1 = *(const ulonglong2*)&sP[kk + 3][rg * 4];
            FMA2P(w1, a1);
            w0 = wn0; a0 = an0;
            w1 = wn1; a1 = an1;
        }
        FMA2P(w0, a0);
        FMA2P(w1, a1);
    }

    __syncthreads();   // sW reads done before sH alias writes

    float bj = bias[j];
#pragma unroll
    for (int r = 0; r < 2; r++) {
        float lo, hi;
        asm("mov.b64 {%0, %1}, %2;" : "=f"(lo), "=f"(hi) : "l"(acc2[r]));
        sH[rg * 4 + 2 * r][j]     = lo + bj;
        sH[rg * 4 + 2 * r + 1][j] = hi + bj;
    }
    __syncthreads();

    // LayerNorm + exact GELU: 16 warps, 1 row each; lane covers 4 columns
    const int warp = threadIdx.x >> 5, lane = threadIdx.x & 31;
    {
        const int row = warp;
        float v[4];
#pragma unroll
        for (int q = 0; q < 4; q++) v[q] = sH[row][lane + 32 * q];

        float s = v[0] + v[1] + v[2] + v[3];
#pragma unroll
        for (int o = 16; o > 0; o >>= 1) s += __shfl_xor_sync(0xffffffffu, s, o);
        float mu = s * (1.0f / 128.0f);

        float vs = 0.f;
#pragma unroll
        for (int q = 0; q < 4; q++) { float d = v[q] - mu; vs += d * d; }
#pragma unroll
        for (int o = 16; o > 0; o >>= 1) vs += __shfl_xor_sync(0xffffffffu, vs, o);
        float inv = rsqrtf(vs * (1.0f / 128.0f) + 1e-5f);

#pragma unroll
        for (int q = 0; q < 4; q++) {
            int col = lane + 32 * q;
            float y = (v[q] - mu) * inv * gamma[col] + beta[col];
            float ge = 0.5f * y * (1.0f + erff(y * 0.70710678118654752f));
            out[(size_t)(g0 + row) * HIDDEN + col] = ge;
        }
    }
}

// ---------------------------------------------------------------------------
extern "C" void kernel_launch(void* const* d_in, const int* in_sizes, int n_in,
                              void* d_out, int out_size) {
    int ix = -1;
    long long maxsz = -1;
    for (int i = 0; i < n_in; i++)
        if ((long long)in_sizes[i] > maxsz) { maxsz = in_sizes[i]; ix = i; }
    const int n_nodes = (int)(maxsz / HIDDEN);

    int ib = -1, iw = -1, vecs[3] = {-1, -1, -1}; int nv = 0;
    for (int i = 0; i < n_in; i++) {
        if (i == ix) continue;
        if (in_sizes[i] == n_nodes) ib = i;
        else if (in_sizes[i] == POOL_DIM * HIDDEN) iw = i;
        else if (in_sizes[i] == HIDDEN && nv < 3) vecs[nv++] = i;
    }

    const float* x     = (const float*)d_in[ix];
    const int*   batch = (const int*)d_in[ib];
    const float* W     = (const float*)d_in[iw];
    const float* b     = (const float*)d_in[vecs[0]];
    const float* gamma = (const float*)d_in[vecs[1]];
    const float* beta  = (const float*)d_in[vecs[2]];
    float* out = (float*)d_out;

    seg_kernel<<<(n_nodes + 511) / 512, 512>>>(batch, n_nodes);
    pool_kernel<<<NGRAPH, 512>>>(x);
    gemm_ln_gelu_kernel<<<NGRAPH / 16, 512>>>(W, b, gamma, beta, out);
}